// round 14
// baseline (speedup 1.0000x reference)
#include <cuda_runtime.h>

// ---------------- constants ----------------
#define C_NUM   80
#define TOPK_N  1000
#define CONF_T  0.05f
#define NMS_THR 0.6f
#define IMG_INV (1.0f/2048.0f)
#define HBINS   16384
#define CAND_CAP 65536
#define N_ALL   3000
#define ROWS0   196608
#define ROWS1   49152
#define ROWS2   12288
#define RTOT    258048
#define GRID1   444      // 148 SMs x 3 resident
#define TPB1    512
#define GATHER_CAP 4096
#define NMS_MAT_CAP 384

// ---------------- device scratch ----------------
__device__ float              g_b[RTOT];
__device__ unsigned int       g_hist[3 * HBINS];    // ub histogram (A1->A2)
__device__ unsigned int       g_hist2[3 * HBINS];   // b histogram  (A3->A4)
__device__ unsigned int       g_hist3[3 * HBINS];   // candidate-score histogram (C->S)
__device__ unsigned int       g_cnt[3];
__device__ unsigned int       g_T1[3];
__device__ unsigned int       g_Tbin[3];
__device__ unsigned long long g_cand[3][CAND_CAP];
__device__ unsigned long long g_topk[3][TOPK_N];
__device__ unsigned int       g_bars[6];             // monotonic epoch barriers

__device__ __forceinline__ float sigm(float x) { return 1.0f / (1.0f + expf(-x)); }

__device__ __forceinline__ void level_of(int grow, int& lvl, int& r) {
    if (grow < ROWS0)              { lvl = 0; r = grow; }
    else if (grow < ROWS0 + ROWS1) { lvl = 1; r = grow - ROWS0; }
    else                           { lvl = 2; r = grow - ROWS0 - ROWS1; }
}

// Monotonic epoch barrier: never reset, graph-replay safe.
__device__ __forceinline__ void gbarm(unsigned int* c) {
    __syncthreads();
    if (threadIdx.x == 0) {
        __threadfence();
        unsigned int idx = atomicAdd(c, 1u);
        unsigned int tgt = (idx / GRID1 + 1u) * GRID1;
        while (*(volatile unsigned int*)c < tgt) __nanosleep(64);
        __threadfence();
    }
    __syncthreads();
}

// Block-wide: largest bin with cumulative-from-top >= K. Valid in tid 0 only.
__device__ int block_thresh(const unsigned int* hist, unsigned int K,
                            unsigned int* csum, unsigned int* cbins,
                            int* s_ch, unsigned int* s_cum) {
    int tid = threadIdx.x;
    if (tid < 256) {
        unsigned int s = 0;
        const unsigned int* hb = hist + tid * 64;
#pragma unroll 8
        for (int i = 0; i < 64; i++) s += hb[i];
        csum[tid] = s;
    }
    __syncthreads();
    if (tid == 0) {
        unsigned int cum = 0;
        int ch = 255;
        for (; ch > 0; ch--) {
            if (cum + csum[ch] >= K) break;
            cum += csum[ch];
        }
        *s_ch = ch; *s_cum = cum;
    }
    __syncthreads();
    int ch = *s_ch;
    if (tid < 64) cbins[tid] = hist[ch * 64 + tid];
    __syncthreads();
    int result = 0;
    if (tid == 0) {
        unsigned int cum = *s_cum;
        int bin = 63;
        for (; bin > 0; bin--) {
            cum += cbins[bin];
            if (cum >= K) break;
        }
        result = ch * 64 + bin;
    }
    __syncthreads();
    return result;
}

// ============ THE kernel: A1 -> A2 -> A3 -> A4 -> C -> S -> N ============
extern __shared__ unsigned char dynb[];

__global__ __launch_bounds__(TPB1, 3)
void k_all(const float* __restrict__ obj0, const float* __restrict__ cls0,
           const float* __restrict__ obj1, const float* __restrict__ cls1,
           const float* __restrict__ obj2, const float* __restrict__ cls2,
           const float* __restrict__ r0, const float* __restrict__ r1,
           const float* __restrict__ r2, const float* __restrict__ anc,
           float* __restrict__ out) {
    int tid = threadIdx.x;
    int bid = blockIdx.x;

    __shared__ unsigned int csum[256];
    __shared__ unsigned int cbins[64];
    __shared__ int s_ch;
    __shared__ unsigned int s_cum, s_B2, s_m;
    __shared__ unsigned int sT[3];

    // ---- A1: obj-only upper bound ub = sqrt(sig(obj)); histogram (1 MB read) ----
    for (int grow = bid * TPB1 + tid; grow < RTOT; grow += GRID1 * TPB1) {
        int lvl, r;
        level_of(grow, lvl, r);
        const float* obj = (lvl == 0) ? obj0 : ((lvl == 1) ? obj1 : obj2);
        float ub = sqrtf(sigm(obj[r]));
        g_b[grow] = ub;
        int bin = (int)(ub * (float)HBINS);
        if (bin > HBINS - 1) bin = HBINS - 1;
        atomicAdd(&g_hist[lvl * HBINS + bin], 1u);
    }

    gbarm(&g_bars[0]);

    // ---- A2: per-level prune threshold T1 = K-th largest ub (blocks 0..2) ----
    if (bid < 3) {
        const unsigned int KSEL[3] = {16384u, 8192u, 4096u};
        int t1 = block_thresh(g_hist + bid * HBINS, KSEL[bid], csum, cbins, &s_ch, &s_cum);
        if (tid == 0) g_T1[bid] = (unsigned int)t1;
    }

    gbarm(&g_bars[1]);

    // ---- A3: zero g_hist (consumed) + true b for pruned rows only (~11 MB) ----
    for (int i = bid * TPB1 + tid; i < 3 * HBINS; i += GRID1 * TPB1) g_hist[i] = 0u;
    {
        if (tid < 3) sT[tid] = *(volatile unsigned int*)&g_T1[tid];
        __syncthreads();
        for (int g = bid * TPB1 + tid; g < RTOT * 4; g += GRID1 * TPB1) {
            int grow = g >> 2;
            int sub = g & 3;
            int lvl, r;
            level_of(grow, lvl, r);
            bool act = ((int)(g_b[grow] * (float)HBINS) >= (int)sT[lvl]);
            float mx = -1e30f;
            if (act) {
                const float* cls = (lvl == 0) ? cls0 : ((lvl == 1) ? cls1 : cls2);
                const float4* c4 = reinterpret_cast<const float4*>(cls) + (size_t)r * 20;
                float4 vb[5];
#pragma unroll
                for (int it = 0; it < 5; it++) vb[it] = c4[it * 4 + sub];
#pragma unroll
                for (int it = 0; it < 5; it++)
                    mx = fmaxf(mx, fmaxf(fmaxf(vb[it].x, vb[it].y), fmaxf(vb[it].z, vb[it].w)));
            }
            // all lanes participate (act is uniform per 4-lane group; shuffles converged)
            mx = fmaxf(mx, __shfl_xor_sync(0xFFFFFFFFu, mx, 1));
            mx = fmaxf(mx, __shfl_xor_sync(0xFFFFFFFFu, mx, 2));
            if (act && sub == 0) {
                const float* obj = (lvl == 0) ? obj0 : ((lvl == 1) ? obj1 : obj2);
                float b = sqrtf(sigm(obj[r]) * sigm(mx));
                g_b[grow] = b;   // overwrite ub with exact b for pruned rows
                int bin = (int)(b * (float)HBINS);
                if (bin > HBINS - 1) bin = HBINS - 1;
                atomicAdd(&g_hist2[lvl * HBINS + bin], 1u);
            }
        }
    }

    gbarm(&g_bars[2]);

    // ---- A4: row-bound threshold Tbin (>=1000 rows in pruned set) ----
    // Correct unconditionally: >=1000 scores >= Tbin exist globally, and any row
    // holding a score >= Tbin has stored value (b or ub) >= it => passes C's gate.
    if (bid < 3) {
        int tb = block_thresh(g_hist2 + bid * HBINS, TOPK_N, csum, cbins, &s_ch, &s_cum);
        if (tid == 0) { g_Tbin[bid] = (unsigned int)tb; g_cnt[bid] = 0u; }
    }

    gbarm(&g_bars[3]);

    // ---- C: zero g_hist2 (consumed) + sparse expansion (4 thr/row) ----
    for (int i = bid * TPB1 + tid; i < 3 * HBINS; i += GRID1 * TPB1) g_hist2[i] = 0u;
    {
        if (tid < 3) sT[tid] = *(volatile unsigned int*)&g_Tbin[tid];
        __syncthreads();
        for (int g = bid * TPB1 + tid; g < RTOT * 4; g += GRID1 * TPB1) {
            int grow = g >> 2;
            int sub = g & 3;
            int lvl, r;
            level_of(grow, lvl, r);
            int B = (int)sT[lvl];
            if ((int)(g_b[grow] * (float)HBINS) < B) continue;
            const float* obj = (lvl == 0) ? obj0 : ((lvl == 1) ? obj1 : obj2);
            const float* cls = (lvl == 0) ? cls0 : ((lvl == 1) ? cls1 : cls2);
            float so = sigm(obj[r]);
            const float4* c4 = reinterpret_cast<const float4*>(cls) + (size_t)r * 20;
            float4 vbuf[5];
#pragma unroll
            for (int it = 0; it < 5; it++) vbuf[it] = c4[it * 4 + sub];
#pragma unroll
            for (int it = 0; it < 5; it++) {
                float vv[4] = {vbuf[it].x, vbuf[it].y, vbuf[it].z, vbuf[it].w};
#pragma unroll
                for (int k = 0; k < 4; k++) {
                    float s = sqrtf(so * sigm(vv[k]));
                    if ((int)(s * (float)HBINS) >= B) {
                        unsigned int sb = __float_as_uint(s);
                        unsigned int p = atomicAdd(&g_cnt[lvl], 1u);
                        if (p < CAND_CAP) {
                            int idx = r * C_NUM + (it * 4 + sub) * 4 + k;
                            g_cand[lvl][p] = ((unsigned long long)sb << 24) |
                                             (unsigned long long)(0xFFFFFF - idx);
                            atomicAdd(&g_hist3[lvl * HBINS + (sb >> 16)], 1u);
                        }
                    }
                }
            }
        }
    }

    gbarm(&g_bars[4]);

    // ---- S: exact top-1000 per level (24 blocks: 8 per level) ----
    if (bid < 24) {
        unsigned long long* sk = (unsigned long long*)dynb;  // 32 KB overlay
        int lvl = bid >> 3;
        int slot = bid & 7;
        unsigned int cnt = *(volatile unsigned int*)&g_cnt[lvl];
        if (cnt > CAND_CAP) cnt = CAND_CAP;
        const unsigned long long* cand = g_cand[lvl];

        int b2 = block_thresh(g_hist3 + lvl * HBINS, TOPK_N, csum, cbins, &s_ch, &s_cum);
        if (tid == 0) { s_B2 = (unsigned int)b2; s_m = 0u; }
        __syncthreads();
        unsigned int B2 = s_B2;

        for (int i = tid; i < (int)cnt; i += TPB1) {
            unsigned long long k = cand[i];
            if ((unsigned int)(k >> 40) >= B2) {
                unsigned int p = atomicAdd(&s_m, 1u);
                if (p < GATHER_CAP) sk[p] = k;
            }
        }
        __syncthreads();
        unsigned int m = s_m;
        int lo = (int)((slot * cnt) >> 3);
        int hi = (int)(((slot + 1) * cnt) >> 3);
        if (m <= GATHER_CAP) {
            for (int i = lo + tid; i < hi; i += TPB1) {
                unsigned long long k = cand[i];
                if ((unsigned int)(k >> 40) >= B2) {
                    int rank = 0;
#pragma unroll 4
                    for (int j = 0; j < (int)m; j++) rank += (sk[j] > k);
                    if (rank < TOPK_N) g_topk[lvl][rank] = k;
                }
            }
        } else {
            for (int ib = lo; ib < hi; ib += TPB1) {
                int i = ib + tid;
                unsigned long long ki = (i < hi) ? cand[i] : 0xFFFFFFFFFFFFFFFFULL;
                int rank = 0;
                for (int cb = 0; cb < (int)cnt; cb += GATHER_CAP) {
                    int mm = min(GATHER_CAP, (int)cnt - cb);
                    __syncthreads();
                    for (int j = tid; j < GATHER_CAP; j += TPB1)
                        sk[j] = (j < mm) ? cand[cb + j] : 0ULL;
                    __syncthreads();
#pragma unroll 4
                    for (int j = 0; j < GATHER_CAP; j++) rank += (sk[j] > ki);
                }
                if (i < hi && rank < TOPK_N) g_topk[lvl][rank] = ki;
            }
        }
    }

    gbarm(&g_bars[5]);
    if (bid >= C_NUM) return;

    // zero candidate histogram for next replay (consumed by phase S)
    for (int i = bid * TPB1 + tid; i < 3 * HBINS; i += C_NUM * TPB1) g_hist3[i] = 0u;

    // ---- N: per-class decode + merge-rank + NMS ----
    {
        int c = bid;
        unsigned long long* gk  = (unsigned long long*)dynb;            // 3000*8 = 24000
        unsigned char* lab      = (unsigned char*)(dynb + 24000);       // 3000 (+pad)
        unsigned long long* lg  = (unsigned long long*)(dynb + 27008);  // 1024*8
        unsigned long long* lg2 = (unsigned long long*)(dynb + 35200);  // 1024*8
        float4* lbox            = (float4*)(dynb + 43392);              // 1024*16
        float*  lare            = (float*)(dynb + 59776);               // 1024*4
        int*    lrnk            = (int*)(dynb + 63872);                 // 1024*4
        unsigned char* lsup     = (unsigned char*)(dynb + 67968);       // 1024
        __shared__ unsigned int s_n;
        __shared__ float s_anc[18];
        if (tid == 0) s_n = 0u;
        if (tid < 18) s_anc[tid] = anc[tid];
        __syncthreads();

        for (int i = tid; i < N_ALL; i += TPB1) {
            int lvl = i / TOPK_N;
            unsigned long long key = g_topk[lvl][i - lvl * TOPK_N];
            unsigned int sb = (unsigned int)(key >> 24);
            float s = __uint_as_float(sb);
            unsigned int zs = (s > CONF_T) ? sb : 0u;
            gk[i] = ((unsigned long long)zs << 12) | (unsigned long long)(4095 - i);
            int idx = 0xFFFFFF - (int)(key & 0xFFFFFFULL);
            lab[i] = (unsigned char)(idx % C_NUM);
        }
        __syncthreads();

        for (int i = tid; i < N_ALL; i += TPB1) {
            if (lab[i] == (unsigned char)c) {
                unsigned int p = atomicAdd(&s_n, 1u);
                if (p < 1024u) lg[p] = gk[i];
            }
        }
        __syncthreads();
        int n = (int)min(s_n, 1024u);
        for (int j = tid; j < n; j += TPB1) {
            unsigned long long kj = lg[j];
            int r = 0;
            for (int k = 0; k < n; k++) r += (lg[k] > kj);
            lg2[r] = kj;
        }
        __syncthreads();

        float offv = (float)c * 100000.0f;
        for (int j = tid; j < n; j += TPB1) {
            unsigned long long gkv = lg2[j];
            int i = 4095 - (int)(gkv & 0xFFFULL);
            int lvl = i / TOPK_N;
            int r = i - lvl * TOPK_N;
            unsigned long long key = g_topk[lvl][r];
            int rank = r;
#pragma unroll
            for (int l = 0; l < 3; l++) {
                if (l == lvl) continue;
                const unsigned long long* arr = gk + l * TOPK_N;
                int blo = 0, bhi = TOPK_N;
                while (blo < bhi) {
                    int mid = (blo + bhi) >> 1;
                    if (arr[mid] > gkv) blo = mid + 1; else bhi = mid;
                }
                rank += blo;
            }
            int idx = 0xFFFFFF - (int)(key & 0xFFFFFFULL);
            int m = idx / C_NUM;
            int a = m % 3;
            int cell = m / 3;
            int W = (lvl == 0) ? 256 : ((lvl == 1) ? 128 : 64);
            float stride = (lvl == 0) ? 8.0f : ((lvl == 1) ? 16.0f : 32.0f);
            int x = cell % W, y = cell / W;
            const float* reg = ((lvl == 0) ? r0 : ((lvl == 1) ? r1 : r2)) + (size_t)m * 4;
            float cx = ((float)x + 0.5f) * stride + (sigm(reg[0]) * 3.0f - 1.5f) * stride;
            float cy = ((float)y + 0.5f) * stride + (sigm(reg[1]) * 3.0f - 1.5f) * stride;
            float bw = expf(reg[2]) * s_anc[lvl * 6 + a * 2 + 0];
            float bh = expf(reg[3]) * s_anc[lvl * 6 + a * 2 + 1];
            float4 b;
            b.x = cx - 0.5f * bw; b.y = cy - 0.5f * bh;
            b.z = cx + 0.5f * bw; b.w = cy + 0.5f * bh;
            out[rank * 4 + 0] = fminf(fmaxf(b.x * IMG_INV, 0.0f), 1.0f);
            out[rank * 4 + 1] = fminf(fmaxf(b.y * IMG_INV, 0.0f), 1.0f);
            out[rank * 4 + 2] = fminf(fmaxf(b.z * IMG_INV, 0.0f), 1.0f);
            out[rank * 4 + 3] = fminf(fmaxf(b.w * IMG_INV, 0.0f), 1.0f);
            out[12000 + rank] = 0.0f;
            out[15000 + rank] = (float)c;
            float4 ob;  // reference's offset-quantized boxes (f32 + label*1e5)
            ob.x = b.x + offv; ob.y = b.y + offv; ob.z = b.z + offv; ob.w = b.w + offv;
            lbox[j] = ob;
            lare[j] = (ob.z - ob.x) * (ob.w - ob.y);
            lrnk[j] = rank;
            lsup[j] = 0;
        }
        __syncthreads();

        if (n <= NMS_MAT_CAP) {
            // bitmask NMS: parallel pairwise matrix + single-thread greedy scan
            unsigned long long* mat = (unsigned long long*)dynb;  // n x 6 words (gk reuse)
            const int NW = 6;
            for (int a = tid; a < n; a += TPB1) {
#pragma unroll
                for (int w = 0; w < NW; w++) mat[a * NW + w] = 0ULL;
                float4 A = lbox[a];
                float arA = lare[a];
                for (int b = a + 1; b < n; b++) {
                    float4 B = lbox[b];
                    float ltx = fmaxf(A.x, B.x), lty = fmaxf(A.y, B.y);
                    float rbx = fminf(A.z, B.z), rby = fminf(A.w, B.w);
                    float wx = fmaxf(rbx - ltx, 0.0f), wy = fmaxf(rby - lty, 0.0f);
                    float inter = wx * wy;
                    float iou = inter / (arA + lare[b] - inter + 1e-12f);
                    if (iou > NMS_THR) mat[a * NW + (b >> 6)] |= 1ULL << (b & 63);
                }
            }
            __syncthreads();
            if (tid == 0) {
                unsigned long long supp[6] = {0, 0, 0, 0, 0, 0};
                for (int a = 0; a < n; a++) {
                    if (!((supp[a >> 6] >> (a & 63)) & 1ULL)) {
                        float sa = __uint_as_float((unsigned int)(lg2[a] >> 12));
                        if (sa > CONF_T) {
                            out[12000 + lrnk[a]] = sa;
#pragma unroll
                            for (int w = 0; w < 6; w++) supp[w] |= mat[a * 6 + w];
                        }
                    }
                }
            }
        } else {
            if (tid < 32) {
                for (int a = 0; a < n; a++) {
                    float sa = __uint_as_float((unsigned int)(lg2[a] >> 12));
                    bool keep = (!lsup[a]) && (sa > CONF_T);
                    if (keep) {
                        if (tid == 0) out[12000 + lrnk[a]] = sa;
                        float4 A = lbox[a];
                        float arA = lare[a];
                        for (int b = a + 1 + tid; b < n; b += 32) {
                            if (lsup[b]) continue;
                            float4 B = lbox[b];
                            float ltx = fmaxf(A.x, B.x), lty = fmaxf(A.y, B.y);
                            float rbx = fminf(A.z, B.z), rby = fminf(A.w, B.w);
                            float wx = fmaxf(rbx - ltx, 0.0f), wy = fmaxf(rby - lty, 0.0f);
                            float inter = wx * wy;
                            float iou = inter / (arA + lare[b] - inter + 1e-12f);
                            if (iou > NMS_THR) lsup[b] = 1;
                        }
                    }
                    __syncwarp();
                }
            }
        }
    }
}

// ---------------- launcher ----------------
extern "C" void kernel_launch(void* const* d_in, const int* in_sizes, int n_in,
                              void* d_out, int out_size) {
    (void)in_sizes; (void)n_in; (void)out_size;
    const float* obj0 = (const float*)d_in[0];
    const float* cls0 = (const float*)d_in[1];
    const float* reg0 = (const float*)d_in[2];
    const float* obj1 = (const float*)d_in[3];
    const float* cls1 = (const float*)d_in[4];
    const float* reg1 = (const float*)d_in[5];
    const float* obj2 = (const float*)d_in[6];
    const float* cls2 = (const float*)d_in[7];
    const float* reg2 = (const float*)d_in[8];
    const float* anc  = (const float*)d_in[9];
    float* out = (float*)d_out;

    const int DYNB = 68992;
    cudaFuncSetAttribute(k_all, cudaFuncAttributeMaxDynamicSharedMemorySize, DYNB);

    k_all<<<GRID1, TPB1, DYNB>>>(obj0, cls0, obj1, cls1, obj2, cls2,
                                 reg0, reg1, reg2, anc, out);
}

// round 16
// speedup vs baseline: 1.0141x; 1.0141x over previous
#include <cuda_runtime.h>

// ---------------- constants ----------------
#define C_NUM   80
#define TOPK_N  1000
#define CONF_T  0.05f
#define NMS_THR 0.6f
#define IMG_INV (1.0f/2048.0f)
#define HBINS   16384
#define CAND_CAP 65536
#define N_ALL   3000
#define ROWS0   196608
#define ROWS1   49152
#define ROWS2   12288
#define RTOT    258048
#define GRID1   296      // 148 SMs x 2 resident (best measured config, R12)
#define TPB1    512
#define SKCAP   4096     // smem candidate cache (32 KB)
#define NMS_MAT_CAP 384

// ---------------- device scratch ----------------
__device__ float              g_b[RTOT];
__device__ unsigned int       g_hist[3 * HBINS];
__device__ unsigned int       g_cnt[3];
__device__ unsigned int       g_Tbin[3];
__device__ unsigned long long g_cand[3][CAND_CAP];
__device__ unsigned long long g_topk[3][TOPK_N];
__device__ unsigned int       g_barA, g_barB, g_barC, g_barD;  // monotonic

__device__ __forceinline__ float sigm(float x) { return 1.0f / (1.0f + expf(-x)); }

__device__ __forceinline__ void level_of(int grow, int& lvl, int& r) {
    if (grow < ROWS0)              { lvl = 0; r = grow; }
    else if (grow < ROWS0 + ROWS1) { lvl = 1; r = grow - ROWS0; }
    else                           { lvl = 2; r = grow - ROWS0 - ROWS1; }
}

// Monotonic epoch barrier: never reset, graph-replay safe.
__device__ __forceinline__ void gbarm(unsigned int* c) {
    __syncthreads();
    if (threadIdx.x == 0) {
        __threadfence();
        unsigned int idx = atomicAdd(c, 1u);
        unsigned int tgt = (idx / GRID1 + 1u) * GRID1;
        while (*(volatile unsigned int*)c < tgt) __nanosleep(64);
        __threadfence();
    }
    __syncthreads();
}

// ============ THE kernel: A -> B -> C -> S -> N ============
extern __shared__ unsigned char dynb[];

__global__ __launch_bounds__(TPB1, 2)
void k_all(const float* __restrict__ obj0, const float* __restrict__ cls0,
           const float* __restrict__ obj1, const float* __restrict__ cls1,
           const float* __restrict__ obj2, const float* __restrict__ cls2,
           const float* __restrict__ r0, const float* __restrict__ r1,
           const float* __restrict__ r2, const float* __restrict__ anc,
           float* __restrict__ out) {
    int tid = threadIdx.x;
    int bid = blockIdx.x;

    __shared__ unsigned int csum[256];
    __shared__ unsigned int cbins[64];
    __shared__ int s_ch;
    __shared__ unsigned int s_cum;
    __shared__ unsigned int sT[3];

    // ---- phase A: per-anchor bound + histogram (4 threads/row, R12 form) ----
    for (int g = bid * TPB1 + tid; g < RTOT * 4; g += GRID1 * TPB1) {
        int grow = g >> 2;
        int sub = g & 3;
        int lvl, r;
        level_of(grow, lvl, r);
        const float* cls = (lvl == 0) ? cls0 : ((lvl == 1) ? cls1 : cls2);
        const float4* c4 = reinterpret_cast<const float4*>(cls) + (size_t)r * 20;
        float4 v0 = c4[sub], v1 = c4[4 + sub], v2 = c4[8 + sub],
               v3 = c4[12 + sub], v4 = c4[16 + sub];
        float mx = fmaxf(fmaxf(v0.x, v0.y), fmaxf(v0.z, v0.w));
        mx = fmaxf(mx, fmaxf(fmaxf(v1.x, v1.y), fmaxf(v1.z, v1.w)));
        mx = fmaxf(mx, fmaxf(fmaxf(v2.x, v2.y), fmaxf(v2.z, v2.w)));
        mx = fmaxf(mx, fmaxf(fmaxf(v3.x, v3.y), fmaxf(v3.z, v3.w)));
        mx = fmaxf(mx, fmaxf(fmaxf(v4.x, v4.y), fmaxf(v4.z, v4.w)));
        mx = fmaxf(mx, __shfl_xor_sync(0xFFFFFFFFu, mx, 1));
        mx = fmaxf(mx, __shfl_xor_sync(0xFFFFFFFFu, mx, 2));
        if (sub == 0) {
            const float* obj = (lvl == 0) ? obj0 : ((lvl == 1) ? obj1 : obj2);
            float b = sqrtf(sigm(obj[r]) * sigm(mx));
            g_b[grow] = b;
            int bin = (int)(b * (float)HBINS);
            if (bin > HBINS - 1) bin = HBINS - 1;
            atomicAdd(&g_hist[lvl * HBINS + bin], 1u);
        }
    }

    gbarm(&g_barA);

    // ---- phase B: per-level row-bound threshold (blocks 0..2) ----
    if (bid < 3) {
        int lvl = bid;
        if (tid < 256) {
            unsigned int s = 0;
            int base = lvl * HBINS + tid * 64;
#pragma unroll 8
            for (int i = 0; i < 64; i++) s += g_hist[base + i];
            csum[tid] = s;
        }
        __syncthreads();
        if (tid == 0) {
            unsigned int cum = 0;
            int ch = 255;
            for (; ch > 0; ch--) {
                if (cum + csum[ch] >= TOPK_N) break;
                cum += csum[ch];
            }
            s_ch = ch; s_cum = cum;
        }
        __syncthreads();
        if (tid < 64) cbins[tid] = g_hist[lvl * HBINS + s_ch * 64 + tid];
        __syncthreads();
        if (tid == 0) {
            unsigned int cum = s_cum;
            int bin = 63;
            for (; bin > 0; bin--) {
                cum += cbins[bin];
                if (cum >= TOPK_N) break;
            }
            g_Tbin[lvl] = (unsigned int)(s_ch * 64 + bin);
            g_cnt[lvl] = 0u;
        }
    }

    gbarm(&g_barB);

    // ---- phase C: zero g_hist (consumed) + sparse expansion (4 thr/row) ----
    for (int i = bid * TPB1 + tid; i < 3 * HBINS; i += GRID1 * TPB1) g_hist[i] = 0u;
    {
        if (tid < 3) sT[tid] = *(volatile unsigned int*)&g_Tbin[tid];
        __syncthreads();
        for (int g = bid * TPB1 + tid; g < RTOT * 4; g += GRID1 * TPB1) {
            int grow = g >> 2;
            int sub = g & 3;
            int lvl, r;
            level_of(grow, lvl, r);
            int B = (int)sT[lvl];
            if ((int)(g_b[grow] * (float)HBINS) < B) continue;  // same discretization as A
            const float* obj = (lvl == 0) ? obj0 : ((lvl == 1) ? obj1 : obj2);
            const float* cls = (lvl == 0) ? cls0 : ((lvl == 1) ? cls1 : cls2);
            float so = sigm(obj[r]);
            const float4* c4 = reinterpret_cast<const float4*>(cls) + (size_t)r * 20;
            float4 vbuf[5];
#pragma unroll
            for (int it = 0; it < 5; it++) vbuf[it] = c4[it * 4 + sub];
#pragma unroll
            for (int it = 0; it < 5; it++) {
                float vv[4] = {vbuf[it].x, vbuf[it].y, vbuf[it].z, vbuf[it].w};
#pragma unroll
                for (int k = 0; k < 4; k++) {
                    float s = sqrtf(so * sigm(vv[k]));
                    if ((int)(s * (float)HBINS) >= B) {
                        unsigned int sb = __float_as_uint(s);
                        unsigned int p = atomicAdd(&g_cnt[lvl], 1u);
                        if (p < CAND_CAP) {
                            int idx = r * C_NUM + (it * 4 + sub) * 4 + k;
                            g_cand[lvl][p] = ((unsigned long long)sb << 24) |
                                             (unsigned long long)(0xFFFFFF - idx);
                        }
                    }
                }
            }
        }
    }

    gbarm(&g_barC);

    // ---- phase S: exact counting-rank select, ALL blocks ----
    // lvl = bid % 3; per-level block counts are 99/99/98 — NS must match exactly
    // (R15 bug: hardcoded NS=99 left level 2's last slice unranked).
    {
        unsigned long long* sk = (unsigned long long*)dynb;  // SKCAP*8 = 32 KB
        int lvl = bid % 3;
        int slot = bid / 3;
        const int NS = (GRID1 - lvl + 2) / 3;     // exact #blocks serving this level
        unsigned int cnt = *(volatile unsigned int*)&g_cnt[lvl];
        if (cnt > CAND_CAP) cnt = CAND_CAP;
        const unsigned long long* cand = g_cand[lvl];
        int lo = (int)(((long long)slot * cnt) / NS);
        int hi = (int)(((long long)(slot + 1) * cnt) / NS);

        if (cnt <= SKCAP) {
            // cache ALL candidates; rank slice exactly
            for (int j = tid; j < (int)cnt; j += TPB1) sk[j] = cand[j];
            __syncthreads();
            for (int i = lo + tid; i < hi; i += TPB1) {
                unsigned long long k = sk[i];
                int rank = 0;
#pragma unroll 4
                for (int j = 0; j < (int)cnt; j++) rank += (sk[j] > k);
                if (rank < TOPK_N) g_topk[lvl][rank] = k;
            }
        } else {
            // rare fallback: chunked rank vs all candidates
            for (int ib = lo; ib < hi; ib += TPB1) {
                int i = ib + tid;
                unsigned long long ki = (i < hi) ? cand[i] : 0xFFFFFFFFFFFFFFFFULL;
                int rank = 0;
                for (int cb = 0; cb < (int)cnt; cb += SKCAP) {
                    int mm = min(SKCAP, (int)cnt - cb);
                    __syncthreads();
                    for (int j = tid; j < SKCAP; j += TPB1)
                        sk[j] = (j < mm) ? cand[cb + j] : 0ULL;
                    __syncthreads();
#pragma unroll 4
                    for (int j = 0; j < SKCAP; j++) rank += (sk[j] > ki);
                }
                if (i < hi && rank < TOPK_N) g_topk[lvl][rank] = ki;
            }
        }
    }

    gbarm(&g_barD);
    if (bid >= C_NUM) return;

    // ---- phase N: per-class decode + merge-rank + NMS (80 blocks) ----
    {
        int c = bid;
        unsigned long long* gk  = (unsigned long long*)dynb;            // 3000*8 = 24000
        unsigned char* lab      = (unsigned char*)(dynb + 24000);       // 3000 (+pad)
        unsigned long long* lg  = (unsigned long long*)(dynb + 27008);  // 1024*8
        unsigned long long* lg2 = (unsigned long long*)(dynb + 35200);  // 1024*8
        float4* lbox            = (float4*)(dynb + 43392);              // 1024*16
        float*  lare            = (float*)(dynb + 59776);               // 1024*4
        int*    lrnk            = (int*)(dynb + 63872);                 // 1024*4
        unsigned char* lsup     = (unsigned char*)(dynb + 67968);       // 1024
        __shared__ unsigned int s_n;
        __shared__ float s_anc[18];
        if (tid == 0) s_n = 0u;
        if (tid < 18) s_anc[tid] = anc[tid];
        __syncthreads();

        for (int i = tid; i < N_ALL; i += TPB1) {
            int lvl = i / TOPK_N;
            unsigned long long key = g_topk[lvl][i - lvl * TOPK_N];
            unsigned int sb = (unsigned int)(key >> 24);
            float s = __uint_as_float(sb);
            unsigned int zs = (s > CONF_T) ? sb : 0u;
            gk[i] = ((unsigned long long)zs << 12) | (unsigned long long)(4095 - i);
            int idx = 0xFFFFFF - (int)(key & 0xFFFFFFULL);
            lab[i] = (unsigned char)(idx % C_NUM);
        }
        __syncthreads();

        for (int i = tid; i < N_ALL; i += TPB1) {
            if (lab[i] == (unsigned char)c) {
                unsigned int p = atomicAdd(&s_n, 1u);
                if (p < 1024u) lg[p] = gk[i];
            }
        }
        __syncthreads();
        int n = (int)min(s_n, 1024u);
        for (int j = tid; j < n; j += TPB1) {
            unsigned long long kj = lg[j];
            int r = 0;
            for (int k = 0; k < n; k++) r += (lg[k] > kj);
            lg2[r] = kj;
        }
        __syncthreads();

        float offv = (float)c * 100000.0f;
        for (int j = tid; j < n; j += TPB1) {
            unsigned long long gkv = lg2[j];
            int i = 4095 - (int)(gkv & 0xFFFULL);
            int lvl = i / TOPK_N;
            int r = i - lvl * TOPK_N;
            unsigned long long key = g_topk[lvl][r];
            int rank = r;
#pragma unroll
            for (int l = 0; l < 3; l++) {
                if (l == lvl) continue;
                const unsigned long long* arr = gk + l * TOPK_N;
                int blo = 0, bhi = TOPK_N;
                while (blo < bhi) {
                    int mid = (blo + bhi) >> 1;
                    if (arr[mid] > gkv) blo = mid + 1; else bhi = mid;
                }
                rank += blo;
            }
            int idx = 0xFFFFFF - (int)(key & 0xFFFFFFULL);
            int m = idx / C_NUM;
            int a = m % 3;
            int cell = m / 3;
            int W = (lvl == 0) ? 256 : ((lvl == 1) ? 128 : 64);
            float stride = (lvl == 0) ? 8.0f : ((lvl == 1) ? 16.0f : 32.0f);
            int x = cell % W, y = cell / W;
            const float* reg = ((lvl == 0) ? r0 : ((lvl == 1) ? r1 : r2)) + (size_t)m * 4;
            float cx = ((float)x + 0.5f) * stride + (sigm(reg[0]) * 3.0f - 1.5f) * stride;
            float cy = ((float)y + 0.5f) * stride + (sigm(reg[1]) * 3.0f - 1.5f) * stride;
            float bw = expf(reg[2]) * s_anc[lvl * 6 + a * 2 + 0];
            float bh = expf(reg[3]) * s_anc[lvl * 6 + a * 2 + 1];
            float4 b;
            b.x = cx - 0.5f * bw; b.y = cy - 0.5f * bh;
            b.z = cx + 0.5f * bw; b.w = cy + 0.5f * bh;
            out[rank * 4 + 0] = fminf(fmaxf(b.x * IMG_INV, 0.0f), 1.0f);
            out[rank * 4 + 1] = fminf(fmaxf(b.y * IMG_INV, 0.0f), 1.0f);
            out[rank * 4 + 2] = fminf(fmaxf(b.z * IMG_INV, 0.0f), 1.0f);
            out[rank * 4 + 3] = fminf(fmaxf(b.w * IMG_INV, 0.0f), 1.0f);
            out[12000 + rank] = 0.0f;
            out[15000 + rank] = (float)c;
            float4 ob;  // reference's offset-quantized boxes (f32 + label*1e5)
            ob.x = b.x + offv; ob.y = b.y + offv; ob.z = b.z + offv; ob.w = b.w + offv;
            lbox[j] = ob;
            lare[j] = (ob.z - ob.x) * (ob.w - ob.y);
            lrnk[j] = rank;
            lsup[j] = 0;
        }
        __syncthreads();

        if (n <= NMS_MAT_CAP) {
            // bitmask NMS: parallel pairwise matrix + single-thread greedy scan
            unsigned long long* mat = (unsigned long long*)dynb;  // n x 6 words (gk reuse)
            const int NW = 6;
            for (int a = tid; a < n; a += TPB1) {
#pragma unroll
                for (int w = 0; w < NW; w++) mat[a * NW + w] = 0ULL;
                float4 A = lbox[a];
                float arA = lare[a];
                for (int b = a + 1; b < n; b++) {
                    float4 B = lbox[b];
                    float ltx = fmaxf(A.x, B.x), lty = fmaxf(A.y, B.y);
                    float rbx = fminf(A.z, B.z), rby = fminf(A.w, B.w);
                    float wx = fmaxf(rbx - ltx, 0.0f), wy = fmaxf(rby - lty, 0.0f);
                    float inter = wx * wy;
                    float iou = inter / (arA + lare[b] - inter + 1e-12f);
                    if (iou > NMS_THR) mat[a * NW + (b >> 6)] |= 1ULL << (b & 63);
                }
            }
            __syncthreads();
            if (tid == 0) {
                unsigned long long supp[6] = {0, 0, 0, 0, 0, 0};
                for (int a = 0; a < n; a++) {
                    if (!((supp[a >> 6] >> (a & 63)) & 1ULL)) {
                        float sa = __uint_as_float((unsigned int)(lg2[a] >> 12));
                        if (sa > CONF_T) {
                            out[12000 + lrnk[a]] = sa;
#pragma unroll
                            for (int w = 0; w < 6; w++) supp[w] |= mat[a * 6 + w];
                        }
                    }
                }
            }
        } else {
            if (tid < 32) {
                for (int a = 0; a < n; a++) {
                    float sa = __uint_as_float((unsigned int)(lg2[a] >> 12));
                    bool keep = (!lsup[a]) && (sa > CONF_T);
                    if (keep) {
                        if (tid == 0) out[12000 + lrnk[a]] = sa;
                        float4 A = lbox[a];
                        float arA = lare[a];
                        for (int b = a + 1 + tid; b < n; b += 32) {
                            if (lsup[b]) continue;
                            float4 B = lbox[b];
                            float ltx = fmaxf(A.x, B.x), lty = fmaxf(A.y, B.y);
                            float rbx = fminf(A.z, B.z), rby = fminf(A.w, B.w);
                            float wx = fmaxf(rbx - ltx, 0.0f), wy = fmaxf(rby - lty, 0.0f);
                            float inter = wx * wy;
                            float iou = inter / (arA + lare[b] - inter + 1e-12f);
                            if (iou > NMS_THR) lsup[b] = 1;
                        }
                    }
                    __syncwarp();
                }
            }
        }
    }
}

// ---------------- launcher ----------------
extern "C" void kernel_launch(void* const* d_in, const int* in_sizes, int n_in,
                              void* d_out, int out_size) {
    (void)in_sizes; (void)n_in; (void)out_size;
    const float* obj0 = (const float*)d_in[0];
    const float* cls0 = (const float*)d_in[1];
    const float* reg0 = (const float*)d_in[2];
    const float* obj1 = (const float*)d_in[3];
    const float* cls1 = (const float*)d_in[4];
    const float* reg1 = (const float*)d_in[5];
    const float* obj2 = (const float*)d_in[6];
    const float* cls2 = (const float*)d_in[7];
    const float* reg2 = (const float*)d_in[8];
    const float* anc  = (const float*)d_in[9];
    float* out = (float*)d_out;

    const int DYNB = 68992;
    cudaFuncSetAttribute(k_all, cudaFuncAttributeMaxDynamicSharedMemorySize, DYNB);

    k_all<<<GRID1, TPB1, DYNB>>>(obj0, cls0, obj1, cls1, obj2, cls2,
                                 reg0, reg1, reg2, anc, out);
}

// round 17
// speedup vs baseline: 1.4269x; 1.4070x over previous
#include <cuda_runtime.h>

// ---------------- constants ----------------
#define C_NUM   80
#define TOPK_N  1000
#define CONF_T  0.05f
#define NMS_THR 0.6f
#define IMG_INV (1.0f/2048.0f)
#define HBINS   16384
#define CAND_CAP 65536
#define N_ALL   3000
#define ROWS0   196608
#define ROWS1   49152
#define ROWS2   12288
#define RTOT    258048
#define GRID1   296      // 148 SMs x 2 resident
#define TPB1    512
#define SKCAP   4096     // smem candidate cache (32 KB)
#define NMS_MAT_CAP 384

// ---------------- device scratch ----------------
__device__ float              g_b[RTOT];
__device__ unsigned int       g_hist[3 * HBINS];
__device__ unsigned int       g_cnt[3];
__device__ unsigned int       g_Tbin[3];
__device__ unsigned long long g_cand[3][CAND_CAP];
__device__ unsigned long long g_topk[3][TOPK_N];
__device__ unsigned int       g_barA, g_barB, g_barC, g_barD;  // monotonic

__device__ __forceinline__ float sigm(float x) { return 1.0f / (1.0f + expf(-x)); }

__device__ __forceinline__ void level_of(int grow, int& lvl, int& r) {
    if (grow < ROWS0)              { lvl = 0; r = grow; }
    else if (grow < ROWS0 + ROWS1) { lvl = 1; r = grow - ROWS0; }
    else                           { lvl = 2; r = grow - ROWS0 - ROWS1; }
}

// Monotonic epoch barrier: never reset, graph-replay safe.
__device__ __forceinline__ void gbarm(unsigned int* c) {
    __syncthreads();
    if (threadIdx.x == 0) {
        __threadfence();
        unsigned int idx = atomicAdd(c, 1u);
        unsigned int tgt = (idx / GRID1 + 1u) * GRID1;
        while (*(volatile unsigned int*)c < tgt) __nanosleep(64);
        __threadfence();
    }
    __syncthreads();
}

// ============ THE kernel: A -> B -> C -> S -> N ============
extern __shared__ unsigned char dynb[];

__global__ __launch_bounds__(TPB1, 2)
void k_all(const float* __restrict__ obj0, const float* __restrict__ cls0,
           const float* __restrict__ obj1, const float* __restrict__ cls1,
           const float* __restrict__ obj2, const float* __restrict__ cls2,
           const float* __restrict__ r0, const float* __restrict__ r1,
           const float* __restrict__ r2, const float* __restrict__ anc,
           float* __restrict__ out) {
    int tid = threadIdx.x;
    int bid = blockIdx.x;

    __shared__ unsigned int csum[256];
    __shared__ unsigned int cbins[64];
    __shared__ int s_ch;
    __shared__ unsigned int s_cum;
    __shared__ unsigned int sT[3];

    // ---- phase A: per-anchor bound + histogram (4 threads/row, R12 form) ----
    for (int g = bid * TPB1 + tid; g < RTOT * 4; g += GRID1 * TPB1) {
        int grow = g >> 2;
        int sub = g & 3;
        int lvl, r;
        level_of(grow, lvl, r);
        const float* cls = (lvl == 0) ? cls0 : ((lvl == 1) ? cls1 : cls2);
        const float4* c4 = reinterpret_cast<const float4*>(cls) + (size_t)r * 20;
        float4 v0 = c4[sub], v1 = c4[4 + sub], v2 = c4[8 + sub],
               v3 = c4[12 + sub], v4 = c4[16 + sub];
        float mx = fmaxf(fmaxf(v0.x, v0.y), fmaxf(v0.z, v0.w));
        mx = fmaxf(mx, fmaxf(fmaxf(v1.x, v1.y), fmaxf(v1.z, v1.w)));
        mx = fmaxf(mx, fmaxf(fmaxf(v2.x, v2.y), fmaxf(v2.z, v2.w)));
        mx = fmaxf(mx, fmaxf(fmaxf(v3.x, v3.y), fmaxf(v3.z, v3.w)));
        mx = fmaxf(mx, fmaxf(fmaxf(v4.x, v4.y), fmaxf(v4.z, v4.w)));
        mx = fmaxf(mx, __shfl_xor_sync(0xFFFFFFFFu, mx, 1));
        mx = fmaxf(mx, __shfl_xor_sync(0xFFFFFFFFu, mx, 2));
        if (sub == 0) {
            const float* obj = (lvl == 0) ? obj0 : ((lvl == 1) ? obj1 : obj2);
            float b = sqrtf(sigm(obj[r]) * sigm(mx));
            g_b[grow] = b;
            int bin = (int)(b * (float)HBINS);
            if (bin > HBINS - 1) bin = HBINS - 1;
            atomicAdd(&g_hist[lvl * HBINS + bin], 1u);
        }
    }

    gbarm(&g_barA);

    // ---- phase B: per-level row-bound threshold (blocks 0..2) ----
    if (bid < 3) {
        int lvl = bid;
        if (tid < 256) {
            unsigned int s = 0;
            int base = lvl * HBINS + tid * 64;
#pragma unroll 8
            for (int i = 0; i < 64; i++) s += g_hist[base + i];
            csum[tid] = s;
        }
        __syncthreads();
        if (tid == 0) {
            unsigned int cum = 0;
            int ch = 255;
            for (; ch > 0; ch--) {
                if (cum + csum[ch] >= TOPK_N) break;
                cum += csum[ch];
            }
            s_ch = ch; s_cum = cum;
        }
        __syncthreads();
        if (tid < 64) cbins[tid] = g_hist[lvl * HBINS + s_ch * 64 + tid];
        __syncthreads();
        if (tid == 0) {
            unsigned int cum = s_cum;
            int bin = 63;
            for (; bin > 0; bin--) {
                cum += cbins[bin];
                if (cum >= TOPK_N) break;
            }
            g_Tbin[lvl] = (unsigned int)(s_ch * 64 + bin);
            g_cnt[lvl] = 0u;
        }
    }

    gbarm(&g_barB);

    // ---- phase C: zero g_hist (consumed) + sparse expansion (4 thr/row) ----
    for (int i = bid * TPB1 + tid; i < 3 * HBINS; i += GRID1 * TPB1) g_hist[i] = 0u;
    {
        if (tid < 3) sT[tid] = *(volatile unsigned int*)&g_Tbin[tid];
        __syncthreads();
        for (int g = bid * TPB1 + tid; g < RTOT * 4; g += GRID1 * TPB1) {
            int grow = g >> 2;
            int sub = g & 3;
            int lvl, r;
            level_of(grow, lvl, r);
            int B = (int)sT[lvl];
            if ((int)(g_b[grow] * (float)HBINS) < B) continue;  // same discretization as A
            const float* obj = (lvl == 0) ? obj0 : ((lvl == 1) ? obj1 : obj2);
            const float* cls = (lvl == 0) ? cls0 : ((lvl == 1) ? cls1 : cls2);
            float so = sigm(obj[r]);
            const float4* c4 = reinterpret_cast<const float4*>(cls) + (size_t)r * 20;
            float4 vbuf[5];
#pragma unroll
            for (int it = 0; it < 5; it++) vbuf[it] = c4[it * 4 + sub];
#pragma unroll
            for (int it = 0; it < 5; it++) {
                float vv[4] = {vbuf[it].x, vbuf[it].y, vbuf[it].z, vbuf[it].w};
#pragma unroll
                for (int k = 0; k < 4; k++) {
                    float s = sqrtf(so * sigm(vv[k]));
                    if ((int)(s * (float)HBINS) >= B) {
                        unsigned int sb = __float_as_uint(s);
                        unsigned int p = atomicAdd(&g_cnt[lvl], 1u);
                        if (p < CAND_CAP) {
                            int idx = r * C_NUM + (it * 4 + sub) * 4 + k;
                            g_cand[lvl][p] = ((unsigned long long)sb << 24) |
                                             (unsigned long long)(0xFFFFFF - idx);
                        }
                    }
                }
            }
        }
    }

    gbarm(&g_barC);

    // ---- phase S: warp-parallel exact counting-rank select, ALL blocks ----
    // Per-level block counts 99/99/98 must match NS exactly (R15 lesson).
    // Warp-per-key: 32 lanes split the cnt-loop -> serial length cnt/32.
    {
        unsigned long long* sk = (unsigned long long*)dynb;  // SKCAP*8 = 32 KB
        int lvl = bid % 3;
        int slot = bid / 3;
        const int NS = (GRID1 - lvl + 2) / 3;     // exact #blocks serving this level
        unsigned int cnt = *(volatile unsigned int*)&g_cnt[lvl];
        if (cnt > CAND_CAP) cnt = CAND_CAP;
        const unsigned long long* cand = g_cand[lvl];
        int lo = (int)(((long long)slot * cnt) / NS);
        int hi = (int)(((long long)(slot + 1) * cnt) / NS);
        int lane = tid & 31;
        int w = tid >> 5;                          // 16 warps

        if (cnt <= SKCAP) {
            for (int j = tid; j < (int)cnt; j += TPB1) sk[j] = cand[j];
            __syncthreads();
            for (int i = lo + w; i < hi; i += 16) {
                unsigned long long k = sk[i];
                int pr = 0;
                for (int j = lane; j < (int)cnt; j += 32) pr += (sk[j] > k);
#pragma unroll
                for (int o = 16; o > 0; o >>= 1)
                    pr += __shfl_down_sync(0xFFFFFFFFu, pr, o);
                if (lane == 0 && pr < TOPK_N) g_topk[lvl][pr] = k;
            }
        } else {
            // rare fallback: warp-parallel rank straight from global (no smem)
            for (int i = lo + w; i < hi; i += 16) {
                unsigned long long k = cand[i];
                int pr = 0;
                for (int j = lane; j < (int)cnt; j += 32) pr += (cand[j] > k);
#pragma unroll
                for (int o = 16; o > 0; o >>= 1)
                    pr += __shfl_down_sync(0xFFFFFFFFu, pr, o);
                if (lane == 0 && pr < TOPK_N) g_topk[lvl][pr] = k;
            }
        }
    }

    gbarm(&g_barD);
    if (bid >= C_NUM) return;

    // ---- phase N: per-class decode + merge-rank + NMS (80 blocks) ----
    {
        int c = bid;
        unsigned long long* gk  = (unsigned long long*)dynb;            // 3000*8 = 24000
        unsigned char* lab      = (unsigned char*)(dynb + 24000);       // 3000 (+pad)
        unsigned long long* lg  = (unsigned long long*)(dynb + 27008);  // 1024*8
        unsigned long long* lg2 = (unsigned long long*)(dynb + 35200);  // 1024*8
        float4* lbox            = (float4*)(dynb + 43392);              // 1024*16
        float*  lare            = (float*)(dynb + 59776);               // 1024*4
        int*    lrnk            = (int*)(dynb + 63872);                 // 1024*4
        unsigned char* lsup     = (unsigned char*)(dynb + 67968);       // 1024
        __shared__ unsigned int s_n;
        __shared__ float s_anc[18];
        if (tid == 0) s_n = 0u;
        if (tid < 18) s_anc[tid] = anc[tid];
        __syncthreads();

        for (int i = tid; i < N_ALL; i += TPB1) {
            int lvl = i / TOPK_N;
            unsigned long long key = g_topk[lvl][i - lvl * TOPK_N];
            unsigned int sb = (unsigned int)(key >> 24);
            float s = __uint_as_float(sb);
            unsigned int zs = (s > CONF_T) ? sb : 0u;
            gk[i] = ((unsigned long long)zs << 12) | (unsigned long long)(4095 - i);
            int idx = 0xFFFFFF - (int)(key & 0xFFFFFFULL);
            lab[i] = (unsigned char)(idx % C_NUM);
        }
        __syncthreads();

        for (int i = tid; i < N_ALL; i += TPB1) {
            if (lab[i] == (unsigned char)c) {
                unsigned int p = atomicAdd(&s_n, 1u);
                if (p < 1024u) lg[p] = gk[i];
            }
        }
        __syncthreads();
        int n = (int)min(s_n, 1024u);
        for (int j = tid; j < n; j += TPB1) {
            unsigned long long kj = lg[j];
            int r = 0;
            for (int k = 0; k < n; k++) r += (lg[k] > kj);
            lg2[r] = kj;
        }
        __syncthreads();

        float offv = (float)c * 100000.0f;
        for (int j = tid; j < n; j += TPB1) {
            unsigned long long gkv = lg2[j];
            int i = 4095 - (int)(gkv & 0xFFFULL);
            int lvl = i / TOPK_N;
            int r = i - lvl * TOPK_N;
            unsigned long long key = g_topk[lvl][r];
            int rank = r;
#pragma unroll
            for (int l = 0; l < 3; l++) {
                if (l == lvl) continue;
                const unsigned long long* arr = gk + l * TOPK_N;
                int blo = 0, bhi = TOPK_N;
                while (blo < bhi) {
                    int mid = (blo + bhi) >> 1;
                    if (arr[mid] > gkv) blo = mid + 1; else bhi = mid;
                }
                rank += blo;
            }
            int idx = 0xFFFFFF - (int)(key & 0xFFFFFFULL);
            int m = idx / C_NUM;
            int a = m % 3;
            int cell = m / 3;
            int W = (lvl == 0) ? 256 : ((lvl == 1) ? 128 : 64);
            float stride = (lvl == 0) ? 8.0f : ((lvl == 1) ? 16.0f : 32.0f);
            int x = cell % W, y = cell / W;
            const float* reg = ((lvl == 0) ? r0 : ((lvl == 1) ? r1 : r2)) + (size_t)m * 4;
            float cx = ((float)x + 0.5f) * stride + (sigm(reg[0]) * 3.0f - 1.5f) * stride;
            float cy = ((float)y + 0.5f) * stride + (sigm(reg[1]) * 3.0f - 1.5f) * stride;
            float bw = expf(reg[2]) * s_anc[lvl * 6 + a * 2 + 0];
            float bh = expf(reg[3]) * s_anc[lvl * 6 + a * 2 + 1];
            float4 b;
            b.x = cx - 0.5f * bw; b.y = cy - 0.5f * bh;
            b.z = cx + 0.5f * bw; b.w = cy + 0.5f * bh;
            out[rank * 4 + 0] = fminf(fmaxf(b.x * IMG_INV, 0.0f), 1.0f);
            out[rank * 4 + 1] = fminf(fmaxf(b.y * IMG_INV, 0.0f), 1.0f);
            out[rank * 4 + 2] = fminf(fmaxf(b.z * IMG_INV, 0.0f), 1.0f);
            out[rank * 4 + 3] = fminf(fmaxf(b.w * IMG_INV, 0.0f), 1.0f);
            out[12000 + rank] = 0.0f;
            out[15000 + rank] = (float)c;
            float4 ob;  // reference's offset-quantized boxes (f32 + label*1e5)
            ob.x = b.x + offv; ob.y = b.y + offv; ob.z = b.z + offv; ob.w = b.w + offv;
            lbox[j] = ob;
            lare[j] = (ob.z - ob.x) * (ob.w - ob.y);
            lrnk[j] = rank;
            lsup[j] = 0;
        }
        __syncthreads();

        if (n <= NMS_MAT_CAP) {
            // bitmask NMS: parallel pairwise matrix + single-thread greedy scan
            unsigned long long* mat = (unsigned long long*)dynb;  // n x 6 words (gk reuse)
            const int NW = 6;
            for (int a = tid; a < n; a += TPB1) {
#pragma unroll
                for (int w = 0; w < NW; w++) mat[a * NW + w] = 0ULL;
                float4 A = lbox[a];
                float arA = lare[a];
                for (int b = a + 1; b < n; b++) {
                    float4 B = lbox[b];
                    float ltx = fmaxf(A.x, B.x), lty = fmaxf(A.y, B.y);
                    float rbx = fminf(A.z, B.z), rby = fminf(A.w, B.w);
                    float wx = fmaxf(rbx - ltx, 0.0f), wy = fmaxf(rby - lty, 0.0f);
                    float inter = wx * wy;
                    float iou = inter / (arA + lare[b] - inter + 1e-12f);
                    if (iou > NMS_THR) mat[a * NW + (b >> 6)] |= 1ULL << (b & 63);
                }
            }
            __syncthreads();
            if (tid == 0) {
                unsigned long long supp[6] = {0, 0, 0, 0, 0, 0};
                for (int a = 0; a < n; a++) {
                    if (!((supp[a >> 6] >> (a & 63)) & 1ULL)) {
                        float sa = __uint_as_float((unsigned int)(lg2[a] >> 12));
                        if (sa > CONF_T) {
                            out[12000 + lrnk[a]] = sa;
#pragma unroll
                            for (int w = 0; w < 6; w++) supp[w] |= mat[a * 6 + w];
                        }
                    }
                }
            }
        } else {
            if (tid < 32) {
                for (int a = 0; a < n; a++) {
                    float sa = __uint_as_float((unsigned int)(lg2[a] >> 12));
                    bool keep = (!lsup[a]) && (sa > CONF_T);
                    if (keep) {
                        if (tid == 0) out[12000 + lrnk[a]] = sa;
                        float4 A = lbox[a];
                        float arA = lare[a];
                        for (int b = a + 1 + tid; b < n; b += 32) {
                            if (lsup[b]) continue;
                            float4 B = lbox[b];
                            float ltx = fmaxf(A.x, B.x), lty = fmaxf(A.y, B.y);
                            float rbx = fminf(A.z, B.z), rby = fminf(A.w, B.w);
                            float wx = fmaxf(rbx - ltx, 0.0f), wy = fmaxf(rby - lty, 0.0f);
                            float inter = wx * wy;
                            float iou = inter / (arA + lare[b] - inter + 1e-12f);
                            if (iou > NMS_THR) lsup[b] = 1;
                        }
                    }
                    __syncwarp();
                }
            }
        }
    }
}

// ---------------- launcher ----------------
extern "C" void kernel_launch(void* const* d_in, const int* in_sizes, int n_in,
                              void* d_out, int out_size) {
    (void)in_sizes; (void)n_in; (void)out_size;
    const float* obj0 = (const float*)d_in[0];
    const float* cls0 = (const float*)d_in[1];
    const float* reg0 = (const float*)d_in[2];
    const float* obj1 = (const float*)d_in[3];
    const float* cls1 = (const float*)d_in[4];
    const float* reg1 = (const float*)d_in[5];
    const float* obj2 = (const float*)d_in[6];
    const float* cls2 = (const float*)d_in[7];
    const float* reg2 = (const float*)d_in[8];
    const float* anc  = (const float*)d_in[9];
    float* out = (float*)d_out;

    const int DYNB = 68992;
    cudaFuncSetAttribute(k_all, cudaFuncAttributeMaxDynamicSharedMemorySize, DYNB);

    k_all<<<GRID1, TPB1, DYNB>>>(obj0, cls0, obj1, cls1, obj2, cls2,
                                 reg0, reg1, reg2, anc, out);
}